// round 7
// baseline (speedup 1.0000x reference)
#include <cuda_runtime.h>
#include <math.h>

#define NB 64
#define HH 30
#define WW 60
#define DD 64

// ---------------- scratch (device globals; no allocation) ----------------
__device__ float g_cell[NB*8*16*DD];        // hseg-cell sums of x (2 MB)
__device__ unsigned g_bcnt[NB*32];          // per-batch arrival counters (monotonic,
                                            // 128B apart; zero-init; never reset -> replay-safe)

// ---------------- geometry LUTs ----------------
__constant__ int c_hstart[8] = {0,6,10,12,15,18,20,24};
__constant__ int c_hlen[8]   = {6,4,2,3,3,2,4,6};
__constant__ int c_wstart[16] = {0,6,10,12,15,18,20,24,30,36,40,42,45,48,50,54};
__constant__ int c_wlen[16]   = {6,4,2,3,3,2,4,6, 6,4,2,3,3,2,4,6};
__constant__ unsigned char c_wseg[60] = {
  0,0,0,0,0,0, 1,1,1,1, 2,2, 3,3,3, 4,4,4, 5,5, 6,6,6,6, 7,7,7,7,7,7,
  8,8,8,8,8,8, 9,9,9,9, 10,10, 11,11,11, 12,12,12, 13,13, 14,14,14,14,
  15,15,15,15,15,15};
// forward maps seg -> pool region index
__constant__ unsigned char c_rh0[8]  = {0,1,1,2,2,3,3,4};
__constant__ unsigned char c_rh1[8]  = {0,0,1,1,1,1,2,2};
__constant__ unsigned char c_rh2[8]  = {0,0,0,0,1,1,1,1};
__constant__ unsigned char c_rw0[16] = {0,1,1,2,2,3,3,4,5,6,6,7,7,8,8,9};
__constant__ unsigned char c_rw1[16] = {0,0,1,1,1,1,2,2,3,3,4,4,4,4,5,5};
__constant__ unsigned char c_rw2[16] = {0,0,0,0,1,1,1,1,2,2,2,2,3,3,3,3};
// inverse maps: region row/col -> [first seg, count]
__constant__ unsigned char p0_hf[5]={0,1,3,5,7},              p0_hc[5]={1,2,2,2,1};
__constant__ unsigned char p0_wf[10]={0,1,3,5,7,8,9,11,13,15},p0_wc[10]={1,2,2,2,1,1,2,2,2,1};
__constant__ unsigned char p1_hf[3]={0,2,6},                  p1_hc[3]={2,4,2};
__constant__ unsigned char p1_wf[6]={0,2,6,8,10,14},          p1_wc[6]={2,4,2,2,4,2};
__constant__ unsigned char p2_hf[2]={0,4},                    p2_hc[2]={4,4};
__constant__ unsigned char p2_wf[4]={0,4,8,12},               p2_wc[4]={4,4,4,4};

// ============ fused kernel: grid = 512 = (batch, hseg), one wave ============
__global__ __launch_bounds__(256, 4) void k_fused(
    const float* __restrict__ x,
    const float* __restrict__ qk_w,
    const float* __restrict__ qk_b,
    const float* __restrict__ score_w,
    const float* __restrict__ score_b,
    const float* __restrict__ noise_x,
    const float* __restrict__ noise_r,
    float* __restrict__ out)
{
    __shared__ __align__(16) float Asm[4096];    // Wq as-is:  A[e*64+j]
    __shared__ __align__(16) float Btsm[4096];   // Wk transposed: Bt[d*64+e]
    __shared__ __align__(16) float rs[20*64];    // region sums; reused as dvec in C
    __shared__ __align__(16) float ush[16*64];   // u vectors
    __shared__ __align__(16) float tsm[16*64];   // t vectors
    __shared__ float qkb[128];
    __shared__ float bsh[16];                    // 0.125*s + score_b
    __shared__ float ash[64];

    int bi  = blockIdx.x;
    int b   = bi >> 3, hs = bi & 7;
    int tid = threadIdx.x;
    int h0  = c_hstart[hs], hl = c_hlen[hs];

    // ---------------- phase A: cell sums (register float4 accumulation) -----
    {
        int ws = tid >> 4, j = tid & 15;         // wseg 0..15, d-quad 0..15
        int a0 = c_wstart[ws], l0 = c_wlen[ws];
        const float4* xb4 = (const float4*)(x + (size_t)(b*HH + h0) * WW * DD);
        float4 acc = make_float4(0.f, 0.f, 0.f, 0.f);
        #pragma unroll
        for (int hh = 0; hh < 6; hh++) {
            if (hh < hl) {
                const float4* xr = xb4 + (hh*WW + a0)*16 + j;
                #pragma unroll
                for (int w = 0; w < 6; w++) {
                    if (w < l0) {
                        float4 v = xr[w*16];
                        acc.x += v.x; acc.y += v.y; acc.z += v.z; acc.w += v.w;
                    }
                }
            }
        }
        ((float4*)(g_cell + (size_t)(b*8 + hs) * 1024))[ws*16 + j] = acc;
    }

    // ---- weight smem fill (overlaps A's tail; pre-barrier) ----
    for (int v = tid; v < 4096; v += 256) Asm[v] = qk_w[v];
    for (int v = tid; v < 4096; v += 256) {
        int e = v >> 6, d = v & 63;
        Btsm[d*64 + e] = qk_w[4096 + v];         // coalesced LDG, strided STS (one-time)
    }
    if (tid < 128) qkb[tid] = qk_b[tid];

    // ---------------- per-batch inter-block barrier -------------------------
    __threadfence();                             // release cell stores
    __syncthreads();
    if (tid == 0) {
        unsigned* cnt = &g_bcnt[b*32];
        unsigned o = atomicAdd(cnt, 1u);
        unsigned target = ((o >> 3) + 1u) << 3;  // round up to next multiple of 8
        while ((int)(atomicAdd(cnt, 0u) - target) < 0) { }
        __threadfence();                         // acquire
    }
    __syncthreads();

    // ---------------- phase B: regions -> u -> t -> (s, dvec) ---------------
    {
        const float* cbp = g_cell + (size_t)b * 8192;
        int rh0 = c_rh0[hs], rh1 = c_rh1[hs], rh2 = c_rh2[hs];
        for (int v = tid; v < 1280; v += 256) {
            int jj = v >> 6, d = v & 63;
            int hf, hc, wf, wc;
            if (jj < 10)      { hf=p0_hf[rh0]; hc=p0_hc[rh0]; wf=p0_wf[jj];   wc=p0_wc[jj]; }
            else if (jj < 16) { int rw=jj-10; hf=p1_hf[rh1]; hc=p1_hc[rh1]; wf=p1_wf[rw]; wc=p1_wc[rw]; }
            else              { int rw=jj-16; hf=p2_hf[rh2]; hc=p2_hc[rh2]; wf=p2_wf[rw]; wc=p2_wc[rw]; }
            float s = 0.f;
            for (int a = 0; a < hc; a++)
                for (int c2 = 0; c2 < wc; c2++)
                    s += cbp[(hf + a)*1024 + (wf + c2)*64 + d];
            rs[v] = s;
        }
        __syncthreads();

        float w0 = score_w[0], w1 = score_w[1], w2 = score_w[2];
        float a0 = w0*(1.f/36.f), a1 = w1*(1.f/100.f), a2 = w2*(1.f/225.f);
        float wsum = w0 + w1 + w2;

        for (int v = tid; v < 1024; v += 256) {
            int ws = v >> 6, f = v & 63;
            ush[v] = a0*rs[(int)c_rw0[ws]*64 + f]
                   + a1*rs[(10 + (int)c_rw1[ws])*64 + f]
                   + a2*rs[(16 + (int)c_rw2[ws])*64 + f];
        }
        __syncthreads();

        // t[c] = Wk u[c] + wsum*bk  (thread = (e, combo-group of 4))
        int e = tid & 63, cg = tid >> 6;
        {
            float init = wsum * qkb[64 + e];
            float t0 = init, t1 = init, t2 = init, t3 = init;
            const float4* u0 = (const float4*)(ush + (cg*4 + 0)*64);
            const float4* u1 = (const float4*)(ush + (cg*4 + 1)*64);
            const float4* u2 = (const float4*)(ush + (cg*4 + 2)*64);
            const float4* u3 = (const float4*)(ush + (cg*4 + 3)*64);
            #pragma unroll
            for (int fq = 0; fq < 16; fq++) {
                int d = fq*4;
                float m0 = Btsm[(d+0)*64 + e];
                float m1 = Btsm[(d+1)*64 + e];
                float m2 = Btsm[(d+2)*64 + e];
                float m3 = Btsm[(d+3)*64 + e];
                float4 ua = u0[fq], ub = u1[fq], uc = u2[fq], ud = u3[fq];
                t0 += m0*ua.x + m1*ua.y + m2*ua.z + m3*ua.w;
                t1 += m0*ub.x + m1*ub.y + m2*ub.z + m3*ub.w;
                t2 += m0*uc.x + m1*uc.y + m2*uc.z + m3*uc.w;
                t3 += m0*ud.x + m1*ud.y + m2*ud.z + m3*ud.w;
            }
            tsm[(cg*4 + 0)*64 + e] = t0;
            tsm[(cg*4 + 1)*64 + e] = t1;
            tsm[(cg*4 + 2)*64 + e] = t2;
            tsm[(cg*4 + 3)*64 + e] = t3;
        }
        __syncthreads();

        // s[c] = bq . t[c]  (warp per 2 combos)
        int lane = tid & 31, warp = tid >> 5;
        float sb = score_b[0];
        for (int c = warp; c < 16; c += 8) {
            float sv = tsm[c*64 + lane]      * qkb[lane]
                     + tsm[c*64 + 32 + lane] * qkb[32 + lane];
            #pragma unroll
            for (int o = 16; o; o >>= 1) sv += __shfl_xor_sync(0xffffffffu, sv, o);
            if (lane == 0) bsh[c] = 0.125f * sv + sb;
        }

        // dvec[c] = Wq^T t[c]  (thread = (j, combo-group of 4)); write into rs
        {
            int j = tid & 63;
            float d0 = 0.f, d1 = 0.f, d2 = 0.f, d3 = 0.f;
            const float4* t0p = (const float4*)(tsm + (cg*4 + 0)*64);
            const float4* t1p = (const float4*)(tsm + (cg*4 + 1)*64);
            const float4* t2p = (const float4*)(tsm + (cg*4 + 2)*64);
            const float4* t3p = (const float4*)(tsm + (cg*4 + 3)*64);
            #pragma unroll
            for (int eq = 0; eq < 16; eq++) {
                int ee = eq*4;
                float a0v = Asm[(ee+0)*64 + j];
                float a1v = Asm[(ee+1)*64 + j];
                float a2v = Asm[(ee+2)*64 + j];
                float a3v = Asm[(ee+3)*64 + j];
                float4 ta = t0p[eq], tb = t1p[eq], tc = t2p[eq], td = t3p[eq];
                d0 += a0v*ta.x + a1v*ta.y + a2v*ta.z + a3v*ta.w;
                d1 += a0v*tb.x + a1v*tb.y + a2v*tb.z + a3v*tb.w;
                d2 += a0v*tc.x + a1v*tc.y + a2v*tc.z + a3v*tc.w;
                d3 += a0v*td.x + a1v*td.y + a2v*td.z + a3v*td.w;
            }
            rs[(cg*4 + 0)*64 + j] = d0;
            rs[(cg*4 + 1)*64 + j] = d1;
            rs[(cg*4 + 2)*64 + j] = d2;
            rs[(cg*4 + 3)*64 + j] = d3;
        }
        __syncthreads();
    }

    // ---------------- phase C: per-pixel dot + gumbel-softmax (x from L2) ---
    {
        float* dsm = rs;                          // dvec[16][64] lives here now
        int lane = tid & 31, warp = tid >> 5;
        int half = lane >> 4, j = lane & 15;

        for (int hh = 0; hh < hl; hh++) {
            int h = h0 + hh;
            int gi = (b*HH + h)*WW + tid;
            float nxv = 0.f, nrv = 0.f;
            if (tid < WW) { nxv = noise_x[gi]; nrv = noise_r[gi]; }

            const float4* xr4 = (const float4*)(x + (size_t)(b*HH + h) * WW * DD);
            int p0 = warp*2 + half;               // 0..15
            int p3 = p0 + 48;
            bool v3 = (p3 < WW);
            float4 a0 = xr4[(p0      )*16 + j];
            float4 a1 = xr4[(p0 + 16)*16 + j];
            float4 a2 = xr4[(p0 + 32)*16 + j];
            float4 a3 = v3 ? xr4[p3*16 + j] : make_float4(0.f,0.f,0.f,0.f);

            int ws0 = c_wseg[p0], ws1 = c_wseg[p0+16], ws2 = c_wseg[p0+32];
            int ws3 = v3 ? (int)c_wseg[p3] : 0;
            float4 d0 = ((const float4*)(dsm + ws0*64))[j];
            float4 d1 = ((const float4*)(dsm + ws1*64))[j];
            float4 d2 = ((const float4*)(dsm + ws2*64))[j];
            float4 d3 = ((const float4*)(dsm + ws3*64))[j];

            float t0 = a0.x*d0.x + a0.y*d0.y + a0.z*d0.z + a0.w*d0.w;
            float t1 = a1.x*d1.x + a1.y*d1.y + a1.z*d1.z + a1.w*d1.w;
            float t2 = a2.x*d2.x + a2.y*d2.y + a2.z*d2.z + a2.w*d2.w;
            float t3 = a3.x*d3.x + a3.y*d3.y + a3.z*d3.z + a3.w*d3.w;

            #pragma unroll
            for (int o = 1; o < 16; o <<= 1) {
                t0 += __shfl_xor_sync(0xffffffffu, t0, o);
                t1 += __shfl_xor_sync(0xffffffffu, t1, o);
                t2 += __shfl_xor_sync(0xffffffffu, t2, o);
                t3 += __shfl_xor_sync(0xffffffffu, t3, o);
            }
            if (j == 0) {
                ash[p0]      = 0.125f*t0 + bsh[ws0];
                ash[p0 + 16] = 0.125f*t1 + bsh[ws1];
                ash[p0 + 32] = 0.125f*t2 + bsh[ws2];
                if (v3) ash[p3] = 0.125f*t3 + bsh[ws3];
            }
            __syncthreads();

            if (tid < WW) {
                float attn = ash[tid];
                float sig  = 1.f / (1.f + expf(-attn));
                float gx   = logf(sig + 1e-8f);
                float gr   = logf(1.f - sig + 1e-8f);
                float nx   = -logf(-logf(nxv + 1e-8f) + 1e-8f);
                float nr   = -logf(-logf(nrv + 1e-8f) + 1e-8f);
                const float invT = 1.f / (0.03f + 1e-8f);
                float l = (gx + nx)*invT - (gr + nr)*invT;
                out[gi] = 1.f / (1.f + expf(-l));
            }
            __syncthreads();                      // ash reuse guard
        }
    }
}

// ---------------- launcher ----------------
extern "C" void kernel_launch(void* const* d_in, const int* in_sizes, int n_in,
                              void* d_out, int out_size) {
    const float* x       = (const float*)d_in[0];   // (64,30,60,64)
    const float* qk_w    = (const float*)d_in[1];   // (128,64)
    const float* qk_b    = (const float*)d_in[2];   // (128,)
    const float* score_w = (const float*)d_in[3];   // (1,3)
    const float* score_b = (const float*)d_in[4];   // (1,)
    const float* noise_x = (const float*)d_in[5];   // (64,1800,1)
    const float* noise_r = (const float*)d_in[6];   // (64,1800,1)
    float* out = (float*)d_out;                     // (64,1800,1)

    k_fused<<<NB*8, 256>>>(x, qk_w, qk_b, score_w, score_b, noise_x, noise_r, out);
}